// round 11
// baseline (speedup 1.0000x reference)
#include <cuda_runtime.h>
#include <cuda_fp16.h>
#include <cstdint>
#include <math.h>

#define BATCH 4
#define CDIM  2048
#define EDIM  1024

// ------------------------- scratch (__device__ globals) ---------------------
__device__ __half g_xh  [(size_t)BATCH * CDIM * EDIM];  // x    [b,C,E] fp16
__device__ __half g_xTh [(size_t)BATCH * CDIM * EDIM];  // xT   [b,E,C] fp16
__device__ __half g_yh  [(size_t)BATCH * CDIM * EDIM];  // y    [b,C,E] fp16
__device__ __half g_zh  [(size_t)BATCH * CDIM * EDIM];  // z    [b,C,E] fp16
__device__ __half g_vxTh[(size_t)BATCH * CDIM * EDIM];  // vxT  [b,E,C] fp16
__device__ __half g_fwh [(size_t)EDIM * EDIM];          // fp16 weights
__device__ __half g_vwh [(size_t)EDIM * EDIM];
__device__ __half g_awh [(size_t)CDIM * CDIM];
__device__ __half g_lgh  [(size_t)BATCH * CDIM * CDIM]; // attn logits*scale f16
__device__ __half g_attnh[(size_t)BATCH * CDIM * CDIM]; // attn weights fp16
__device__ int    g_mask_mode;                          // 0=u8, 1=i32(words), 2=f32
__device__ int    g_sched;                              // dynamic tile counter
__device__ int    g_rbcnt[64];                          // row-block completion ctrs

// ------------------------- helpers ------------------------------------------
__device__ __forceinline__ uint32_t smem_u32(const void* p) {
    uint32_t a;
    asm("{ .reg .u64 t; cvta.to.shared.u64 t, %1; cvt.u32.u64 %0, t; }"
        : "=r"(a) : "l"(p));
    return a;
}
__device__ __forceinline__ void ldm_x4(unsigned* r, uint32_t addr) {
    asm volatile("ldmatrix.sync.aligned.m8n8.x4.shared.b16 {%0,%1,%2,%3}, [%4];"
                 : "=r"(r[0]), "=r"(r[1]), "=r"(r[2]), "=r"(r[3]) : "r"(addr));
}
__device__ __forceinline__ void mma_f16(float* c, const unsigned* a, const unsigned* b) {
    asm volatile(
        "mma.sync.aligned.m16n8k16.row.col.f32.f16.f16.f32 "
        "{%0,%1,%2,%3}, {%4,%5,%6,%7}, {%8,%9}, {%0,%1,%2,%3};"
        : "+f"(c[0]), "+f"(c[1]), "+f"(c[2]), "+f"(c[3])
        : "r"(a[0]), "r"(a[1]), "r"(a[2]), "r"(a[3]), "r"(b[0]), "r"(b[1]));
}
#define CP_COMMIT() asm volatile("cp.async.commit_group;" ::: "memory")
#define CP_WAIT(n)  asm volatile("cp.async.wait_group %0;" :: "n"(n) : "memory")

// ------------------------- mask-mode detection ------------------------------
__global__ void detect_mask_kernel(const unsigned int* __restrict__ w, int nwords)
{
    __shared__ int sawFloat, sawMulti;
    if (threadIdx.x == 0) { sawFloat = 0; sawMulti = 0; }
    __syncthreads();
    for (int i = threadIdx.x; i < nwords; i += blockDim.x) {
        unsigned int v = w[i];
        if (v == 0x3F800000u) atomicOr(&sawFloat, 1);
        else if (v > 1u)      atomicOr(&sawMulti, 1);
    }
    __syncthreads();
    if (threadIdx.x == 0)
        g_mask_mode = sawFloat ? 2 : (sawMulti ? 0 : 1);
}

// ---------------- f32 -> f16 conversion of the 3 weight matrices ------------
__global__ void cvt3_kernel(const float4* __restrict__ w1, __half2* __restrict__ o1, int n1,
                            const float4* __restrict__ w2, __half2* __restrict__ o2, int n2,
                            const float4* __restrict__ w3, __half2* __restrict__ o3, int n3)
{
    const int total = n1 + n2 + n3;
    for (int i = blockIdx.x * 256 + threadIdx.x; i < total; i += gridDim.x * 256) {
        const float4* src; __half2* dst; int j = i;
        if (j < n1)            { src = w1; dst = o1; }
        else if ((j -= n1) < n2) { src = w2; dst = o2; }
        else                   { j -= n2; src = w3; dst = o3; }
        float4 v = src[j];
        dst[2 * j]     = __floats2half2_rn(v.x, v.y);
        dst[2 * j + 1] = __floats2half2_rn(v.z, v.w);
    }
}

// --------------- transpose+cvt: x f32 -> xh [C,E] f16 AND xTh [E,C] f16 -----
__global__ void transpose_dual_kernel(const float* __restrict__ in,
                                      __half* __restrict__ xh,
                                      __half* __restrict__ xTh)
{
    __shared__ float t[32][68];          // [c][e], padded
    const long long boff = (long long)blockIdx.z * CDIM * EDIM;
    const int e0 = blockIdx.x * 64, c0 = blockIdx.y * 32;
    const int tx = threadIdx.x, ty = threadIdx.y;   // (16, 16)

    #pragma unroll
    for (int j = 0; j < 2; j++) {
        const int c = c0 + ty + j * 16;
        float4 v = *reinterpret_cast<const float4*>(
            in + boff + (long long)c * EDIM + e0 + 4 * tx);
        t[ty + j * 16][4 * tx + 0] = v.x;
        t[ty + j * 16][4 * tx + 1] = v.y;
        t[ty + j * 16][4 * tx + 2] = v.z;
        t[ty + j * 16][4 * tx + 3] = v.w;
        __half2 h0 = __floats2half2_rn(v.x, v.y);
        __half2 h1 = __floats2half2_rn(v.z, v.w);
        uint2 u;
        u.x = *reinterpret_cast<unsigned*>(&h0);
        u.y = *reinterpret_cast<unsigned*>(&h1);
        *reinterpret_cast<uint2*>(xh + boff + (long long)c * EDIM + e0 + 4 * tx) = u;
    }
    __syncthreads();
    #pragma unroll
    for (int j = 0; j < 4; j++) {
        const int er = ty + j * 16;      // e within tile (0..63)
        __half2 h = __floats2half2_rn(t[2 * tx][er], t[2 * tx + 1][er]);
        *reinterpret_cast<__half2*>(
            xTh + boff + (long long)(e0 + er) * CDIM + c0 + 2 * tx) = h;
    }
}

// ------------- in-kernel softmax for one 128-row logit strip -----------------
// 128 threads; warp w handles rows w, w+4, ... Each lane owns 64 contiguous k.
__device__ __noinline__ void softmax_rowblock(
    const __half* __restrict__ lg, __half* __restrict__ outp,
    const void* __restrict__ mask_raw, int mode, int batch, int by, int tid)
{
    const int lane = tid & 31, wid = tid >> 5;
    for (int r = wid; r < 128; r += 4) {
        const long long row = (long long)batch * CDIM + (long long)by * 128 + r;
        const uint4* lrow = reinterpret_cast<const uint4*>(lg + row * CDIM);
        float v[64];
        #pragma unroll
        for (int j = 0; j < 8; j++) {
            uint4 raw = lrow[lane * 8 + j];
            float f[8];
            __half2 h;
            h = *reinterpret_cast<__half2*>(&raw.x); f[0] = __low2float(h); f[1] = __high2float(h);
            h = *reinterpret_cast<__half2*>(&raw.y); f[2] = __low2float(h); f[3] = __high2float(h);
            h = *reinterpret_cast<__half2*>(&raw.z); f[4] = __low2float(h); f[5] = __high2float(h);
            h = *reinterpret_cast<__half2*>(&raw.w); f[6] = __low2float(h); f[7] = __high2float(h);
            bool mk[8];
            if (mode == 0) {
                uint2 m = reinterpret_cast<const uint2*>(
                    (const unsigned char*)mask_raw + row * CDIM)[lane * 8 + j];
                #pragma unroll
                for (int i = 0; i < 4; i++) {
                    mk[i]     = ((m.x >> (8 * i)) & 0xFFu) != 0u;
                    mk[4 + i] = ((m.y >> (8 * i)) & 0xFFu) != 0u;
                }
            } else {
                const uint4* mw = reinterpret_cast<const uint4*>(mask_raw) + row * (CDIM / 4);
                uint4 a = mw[(lane * 8 + j) * 2];
                uint4 b = mw[(lane * 8 + j) * 2 + 1];
                mk[0] = a.x != 0u; mk[1] = a.y != 0u; mk[2] = a.z != 0u; mk[3] = a.w != 0u;
                mk[4] = b.x != 0u; mk[5] = b.y != 0u; mk[6] = b.z != 0u; mk[7] = b.w != 0u;
            }
            #pragma unroll
            for (int i = 0; i < 8; i++)
                v[j * 8 + i] = mk[i] ? -INFINITY : f[i];
        }
        float lmax = -INFINITY;
        #pragma unroll
        for (int i = 0; i < 64; i++) lmax = fmaxf(lmax, v[i]);
        #pragma unroll
        for (int o = 16; o > 0; o >>= 1)
            lmax = fmaxf(lmax, __shfl_xor_sync(0xFFFFFFFFu, lmax, o));
        float lsum = 0.f;
        #pragma unroll
        for (int i = 0; i < 64; i++) {
            v[i] = (v[i] == -INFINITY) ? 0.f : __expf(v[i] - lmax);
            lsum += v[i];
        }
        #pragma unroll
        for (int o = 16; o > 0; o >>= 1)
            lsum += __shfl_xor_sync(0xFFFFFFFFu, lsum, o);
        const float inv = 1.f / lsum;
        uint4* orow = reinterpret_cast<uint4*>(outp + row * CDIM);
        #pragma unroll
        for (int j = 0; j < 8; j++) {
            __half2 h0 = __floats2half2_rn(v[j * 8 + 0] * inv, v[j * 8 + 1] * inv);
            __half2 h1 = __floats2half2_rn(v[j * 8 + 2] * inv, v[j * 8 + 3] * inv);
            __half2 h2 = __floats2half2_rn(v[j * 8 + 4] * inv, v[j * 8 + 5] * inv);
            __half2 h3 = __floats2half2_rn(v[j * 8 + 6] * inv, v[j * 8 + 7] * inv);
            uint4 w;
            w.x = *reinterpret_cast<unsigned*>(&h0);
            w.y = *reinterpret_cast<unsigned*>(&h1);
            w.z = *reinterpret_cast<unsigned*>(&h2);
            w.w = *reinterpret_cast<unsigned*>(&h3);
            orow[lane * 8 + j] = w;
        }
    }
}

// ---------------------------------------------------------------------------
// Persistent FP16 mma.sync NT GEMM (multi-op), optional dynamic LPT scheduling
// and optional fused softmax on row-block completion.
// Block tile 128x128, 128 thr, 4 warps (2x2, warp 64x64), K-chunk 64,
// cp.async 3-stage, ldmatrix.x4 with register double-buffering.
// biasMode: 0=none, 1=col, 2=row. outMode: 0=f16, 1=f32, 2=f16*SCALE.
// ---------------------------------------------------------------------------
#define STAGE_BYTES 32768                 // A 16KB + B 16KB
#define NSTAGE 3
#define SMEM_DYN   (NSTAGE * STAGE_BYTES) // 96 KB

#define ATT_SCALE 0.022097086912079612f   // 1/sqrt(2048)

struct GOp {
    const __half* A; const __half* B; const float* bias; void* C;
    long long sA, sB, sC;
    int K, lda, ldb, ldc, biasMode, outMode, nbx, ntb /*nbx*nby*/, off;
};
struct GParams {
    GOp op[3]; int nops; int total; int dyn; int doSoftmax;
    const __half* lgS; __half* attnS; const void* maskS;
};

__device__ __forceinline__ void cp_tile_h(uint32_t base, const __half* g, int ld, int tid)
{
    #pragma unroll
    for (int l = 0; l < 8; l++) {
        int idx = tid + l * 128;          // 0..1023
        int r  = idx >> 3;                // 0..127
        int cb = (idx & 7) << 4;          // byte col 0..112
        uint32_t dst = base + r * 128 + (cb ^ ((r & 7) << 4));
        const __half* src = g + (long long)r * ld + (cb >> 1);
        asm volatile("cp.async.cg.shared.global [%0], [%1], 16;"
                     :: "r"(dst), "l"(src) : "memory");
    }
}

__global__ void __launch_bounds__(128, 2)
gemm_any(GParams P)
{
    extern __shared__ char sm[];
    const uint32_t smem0 = smem_u32(sm);
    __shared__ int s_tile;

    const int tid  = threadIdx.x;
    const int lane = tid & 31;
    const int wid  = tid >> 5;
    const int wm   = (wid & 1) * 64;
    const int wn   = (wid >> 1) * 64;
    const int g    = lane >> 2;
    const int tc   = lane & 3;

    // ldmatrix per-lane address components
    const int arow = (lane & 15);
    const int akx  = (lane >> 4) << 4;
    const int brow = (lane & 7) + ((lane >> 4) & 1) * 8;
    const int bkx  = ((lane >> 3) & 1) << 4;

    const int mode = g_mask_mode;
    int tstat = blockIdx.x;

    for (;;) {
        int t;
        __syncthreads();                  // stage + s_tile protection
        if (P.dyn) {
            if (tid == 0) s_tile = atomicAdd(&g_sched, 1);
            __syncthreads();
            t = s_tile;
        } else {
            t = tstat; tstat += gridDim.x;
        }
        if (t >= P.total) break;

        int oi = 0;
        if (P.nops > 1 && t >= P.op[1].off) oi = 1;
        if (P.nops > 2 && t >= P.op[2].off) oi = 2;
        const GOp o = P.op[oi];
        int rem = t - o.off;
        const int batch = rem / o.ntb;
        rem -= batch * o.ntb;
        const int bx = rem % o.nbx;
        const int by = rem / o.nbx;

        const __half* A = o.A + (long long)batch * o.sA + (long long)(by * 128) * o.lda;
        const __half* B = o.B + (long long)batch * o.sB + (long long)(bx * 128) * o.ldb;

        float acc[4][8][4];
        #pragma unroll
        for (int i = 0; i < 4; i++)
            #pragma unroll
            for (int j = 0; j < 8; j++)
                #pragma unroll
                for (int k = 0; k < 4; k++) acc[i][j][k] = 0.f;

        const int nk = o.K >> 6;          // K-chunks of 64

        cp_tile_h(smem0,         A, o.lda, tid);
        cp_tile_h(smem0 + 16384, B, o.ldb, tid);
        CP_COMMIT();
        cp_tile_h(smem0 + STAGE_BYTES,         A + 64, o.lda, tid);
        cp_tile_h(smem0 + STAGE_BYTES + 16384, B + 64, o.ldb, tid);
        CP_COMMIT();

        int s = 0;
        for (int i = 0; i < nk; i++) {
            if (i + 1 < nk) CP_WAIT(1); else CP_WAIT(0);
            __syncthreads();
            if (i + 2 < nk) {
                int s2 = s + 2; if (s2 >= NSTAGE) s2 -= NSTAGE;
                const uint32_t nb = smem0 + s2 * STAGE_BYTES;
                cp_tile_h(nb,         A + (i + 2) * 64, o.lda, tid);
                cp_tile_h(nb + 16384, B + (i + 2) * 64, o.ldb, tid);
                CP_COMMIT();
            }

            const uint32_t As = smem0 + s * STAGE_BYTES;
            const uint32_t Bs = As + 16384;

            unsigned a0[4][4], b0[4][4], a1[4][4], b1[4][4];
            #pragma unroll
            for (int mf = 0; mf < 4; mf++) {
                int r = wm + mf * 16 + arow;
                ldm_x4(a0[mf], As + r * 128 + ((0 + akx) ^ ((r & 7) << 4)));
            }
            #pragma unroll
            for (int p = 0; p < 4; p++) {
                int r = wn + p * 16 + brow;
                ldm_x4(b0[p], Bs + r * 128 + ((0 + bkx) ^ ((r & 7) << 4)));
            }
            #pragma unroll
            for (int ks = 0; ks < 4; ks++) {
                unsigned (&ac)[4][4] = (ks & 1) ? a1 : a0;
                unsigned (&bc)[4][4] = (ks & 1) ? b1 : b0;
                unsigned (&an)[4][4] = (ks & 1) ? a0 : a1;
                unsigned (&bn)[4][4] = (ks & 1) ? b0 : b1;
                if (ks < 3) {
                    const int kb = (ks + 1) * 32;
                    #pragma unroll
                    for (int mf = 0; mf < 4; mf++) {
                        int r = wm + mf * 16 + arow;
                        ldm_x4(an[mf], As + r * 128 + ((kb + akx) ^ ((r & 7) << 4)));
                    }
                    #pragma unroll
                    for (int p = 0; p < 4; p++) {
                        int r = wn + p * 16 + brow;
                        ldm_x4(bn[p], Bs + r * 128 + ((kb + bkx) ^ ((r & 7) << 4)));
                    }
                }
                #pragma unroll
                for (int mf = 0; mf < 4; mf++)
                    #pragma unroll
                    for (int p = 0; p < 4; p++) {
                        mma_f16(acc[mf][2 * p],     ac[mf], &bc[p][0]);
                        mma_f16(acc[mf][2 * p + 1], ac[mf], &bc[p][2]);
                    }
            }
            if (++s == NSTAGE) s = 0;
        }

        // ------------------------- epilogue ---------------------------------
        #pragma unroll
        for (int mf = 0; mf < 4; mf++) {
            #pragma unroll
            for (int nf = 0; nf < 8; nf++) {
                const int r0 = by * 128 + wm + mf * 16 + g;
                const int c  = bx * 128 + wn + nf * 8 + 2 * tc;
                float v0 = acc[mf][nf][0], v1 = acc[mf][nf][1];
                float v2 = acc[mf][nf][2], v3 = acc[mf][nf][3];
                if (o.biasMode == 1) {
                    const float b0 = o.bias[c], b1 = o.bias[c + 1];
                    v0 += b0; v1 += b1; v2 += b0; v3 += b1;
                } else if (o.biasMode == 2) {
                    const float br0 = o.bias[r0], br1 = o.bias[r0 + 8];
                    v0 += br0; v1 += br0; v2 += br1; v3 += br1;
                }
                if (o.outMode == 1) {
                    float* Cb = (float*)o.C + (long long)batch * o.sC;
                    *reinterpret_cast<float2*>(Cb + (long long)r0 * o.ldc + c)       = make_float2(v0, v1);
                    *reinterpret_cast<float2*>(Cb + (long long)(r0 + 8) * o.ldc + c) = make_float2(v2, v3);
                } else {
                    const float scl = (o.outMode == 2) ? ATT_SCALE : 1.f;
                    __half* Cb = (__half*)o.C + (long long)batch * o.sC;
                    *reinterpret_cast<__half2*>(Cb + (long long)r0 * o.ldc + c)       = __floats2half2_rn(v0 * scl, v1 * scl);
                    *reinterpret_cast<__half2*>(Cb + (long long)(r0 + 8) * o.ldc + c) = __floats2half2_rn(v2 * scl, v3 * scl);
                }
            }
        }

        // ------- fused softmax: run when this row-block's 16 tiles done ------
        if (P.doSoftmax) {
            __threadfence();
            if (tid == 0) s_tile = atomicAdd(&g_rbcnt[batch * 16 + by], 1);
            __syncthreads();
            const int done = s_tile;
            if (done == 15) {
                __threadfence();
                softmax_rowblock(P.lgS, P.attnS, P.maskS, mode, batch, by, tid);
            }
        }
    }
}

// ---------------------------------------------------------------------------
extern "C" void kernel_launch(void* const* d_in, const int* in_sizes, int n_in,
                              void* d_out, int out_size)
{
    const float* x     = (const float*)d_in[0];   // [B,C,E]
    const float* fc_w  = (const float*)d_in[1];   // [E,E]
    const float* fc_b  = (const float*)d_in[2];   // [E]
    const float* alt_w = (const float*)d_in[3];   // [C,C]
    const float* alt_b = (const float*)d_in[4];   // [C]
    const float* v_w   = (const float*)d_in[5];   // [E,E]
    const float* v_b   = (const float*)d_in[6];   // [E]
    const void*  mask  = d_in[7];                 // [B,C,C] bool (encoding detected)
    float* out = (float*)d_out;                   // [B,C,E]

    __half *xh, *xTh, *yh, *zh, *vxTh, *fwh, *vwh, *awh, *lgh, *attnh;
    void *schedp, *rbp;
    cudaGetSymbolAddress((void**)&xh,    g_xh);
    cudaGetSymbolAddress((void**)&xTh,   g_xTh);
    cudaGetSymbolAddress((void**)&yh,    g_yh);
    cudaGetSymbolAddress((void**)&zh,    g_zh);
    cudaGetSymbolAddress((void**)&vxTh,  g_vxTh);
    cudaGetSymbolAddress((void**)&fwh,   g_fwh);
    cudaGetSymbolAddress((void**)&vwh,   g_vwh);
    cudaGetSymbolAddress((void**)&awh,   g_awh);
    cudaGetSymbolAddress((void**)&lgh,   g_lgh);
    cudaGetSymbolAddress((void**)&attnh, g_attnh);
    cudaGetSymbolAddress(&schedp, g_sched);
    cudaGetSymbolAddress(&rbp,    g_rbcnt);

    cudaFuncSetAttribute(gemm_any, cudaFuncAttributeMaxDynamicSharedMemorySize, SMEM_DYN);

    int smCount = 148;
    {
        int dev = 0;
        cudaGetDevice(&dev);
        cudaDeviceGetAttribute(&smCount, cudaDevAttrMultiProcessorCount, dev);
    }
    const int gridP = smCount * 2;       // persistent grid (2 CTAs/SM resident)

    const long long sCE = (long long)CDIM * EDIM;
    const long long sCC = (long long)CDIM * CDIM;

    // 0) counters + mask encoding + fp16 conversions
    cudaMemsetAsync(schedp, 0, sizeof(int));
    cudaMemsetAsync(rbp,    0, 64 * sizeof(int));
    detect_mask_kernel<<<1, 256>>>((const unsigned int*)mask, 16384);
    cvt3_kernel<<<1024, 256>>>(
        (const float4*)fc_w,  (__half2*)fwh, (EDIM * EDIM) / 4,
        (const float4*)v_w,   (__half2*)vwh, (EDIM * EDIM) / 4,
        (const float4*)alt_w, (__half2*)awh, (CDIM * CDIM) / 4);
    transpose_dual_kernel<<<dim3(EDIM / 64, CDIM / 32, BATCH), dim3(16, 16)>>>(x, xh, xTh);

    // 1-3) merged GEMMs, dynamic LPT scheduling (heavy z tiles first; 1536 tiles)
    {
        GParams P; P.nops = 3; P.dyn = 1; P.doSoftmax = 0;
        P.lgS = nullptr; P.attnS = nullptr; P.maskS = nullptr;
        // z (K=2048, heavy) first
        P.op[0] = { awh, xTh, alt_b, zh,   0,   sCE, sCE, CDIM, CDIM, CDIM, EDIM, 2, 0, EDIM / 128, (EDIM / 128) * (CDIM / 128), 0 };
        P.op[1] = { xh,  fwh, fc_b,  yh,   sCE, 0,   sCE, EDIM, EDIM, EDIM, EDIM, 1, 0, EDIM / 128, (EDIM / 128) * (CDIM / 128), 512 };
        P.op[2] = { vwh, xh,  v_b,   vxTh, 0,   sCE, sCE, EDIM, EDIM, EDIM, CDIM, 2, 0, CDIM / 128, (CDIM / 128) * (EDIM / 128), 1024 };
        P.total = 1536;
        gemm_any<<<gridP, 128, SMEM_DYN>>>(P);
    }

    // 4) logits*scale -> f16, with fused softmax on row-block completion
    {
        GParams P; P.nops = 1; P.dyn = 0; P.doSoftmax = 1;
        P.lgS = lgh; P.attnS = attnh; P.maskS = mask;
        P.op[0] = { yh, zh, nullptr, lgh, sCE, sCE, sCC, EDIM, EDIM, EDIM, CDIM, 0, 2, CDIM / 128, (CDIM / 128) * (CDIM / 128), 0 };
        P.total = 1024;
        gemm_any<<<gridP, 128, SMEM_DYN>>>(P);
    }

    // 5) out[c,e] = sum_k attn[c,k]*vxT[e,k]  (f32 out, 512 tiles)
    {
        GParams P; P.nops = 1; P.dyn = 0; P.doSoftmax = 0;
        P.lgS = nullptr; P.attnS = nullptr; P.maskS = nullptr;
        P.op[0] = { attnh, vxTh, nullptr, out, sCC, sCE, sCE, CDIM, CDIM, CDIM, EDIM, 0, 1, EDIM / 128, (EDIM / 128) * (CDIM / 128), 0 };
        P.total = 512;
        gemm_any<<<gridP, 128, SMEM_DYN>>>(P);
    }
}

// round 12
// speedup vs baseline: 2.0923x; 2.0923x over previous
#include <cuda_runtime.h>
#include <cuda_fp16.h>
#include <cstdint>
#include <math.h>

#define BATCH 4
#define CDIM  2048
#define EDIM  1024

// ------------------------- scratch (__device__ globals) ---------------------
__device__ __half g_xh  [(size_t)BATCH * CDIM * EDIM];  // x    [b,C,E] fp16
__device__ __half g_xTh [(size_t)BATCH * CDIM * EDIM];  // xT   [b,E,C] fp16
__device__ __half g_yh  [(size_t)BATCH * CDIM * EDIM];  // y    [b,C,E] fp16
__device__ __half g_zh  [(size_t)BATCH * CDIM * EDIM];  // z    [b,C,E] fp16
__device__ __half g_vxTh[(size_t)BATCH * CDIM * EDIM];  // vxT  [b,E,C] fp16
__device__ __half g_fwh [(size_t)EDIM * EDIM];          // fp16 weights
__device__ __half g_vwh [(size_t)EDIM * EDIM];
__device__ __half g_awh [(size_t)CDIM * CDIM];
__device__ __half g_lgh  [(size_t)BATCH * CDIM * CDIM]; // attn logits*scale f16
__device__ __half g_attnh[(size_t)BATCH * CDIM * CDIM]; // attn weights fp16
__device__ int    g_mask_mode;                          // 0=u8, 1=i32(words), 2=f32

// ------------------------- helpers ------------------------------------------
__device__ __forceinline__ uint32_t smem_u32(const void* p) {
    uint32_t a;
    asm("{ .reg .u64 t; cvta.to.shared.u64 t, %1; cvt.u32.u64 %0, t; }"
        : "=r"(a) : "l"(p));
    return a;
}
__device__ __forceinline__ void ldm_x4(unsigned* r, uint32_t addr) {
    asm volatile("ldmatrix.sync.aligned.m8n8.x4.shared.b16 {%0,%1,%2,%3}, [%4];"
                 : "=r"(r[0]), "=r"(r[1]), "=r"(r[2]), "=r"(r[3]) : "r"(addr));
}
__device__ __forceinline__ void mma_f16(float* c, const unsigned* a, const unsigned* b) {
    asm volatile(
        "mma.sync.aligned.m16n8k16.row.col.f32.f16.f16.f32 "
        "{%0,%1,%2,%3}, {%4,%5,%6,%7}, {%8,%9}, {%0,%1,%2,%3};"
        : "+f"(c[0]), "+f"(c[1]), "+f"(c[2]), "+f"(c[3])
        : "r"(a[0]), "r"(a[1]), "r"(a[2]), "r"(a[3]), "r"(b[0]), "r"(b[1]));
}
#define CP_COMMIT() asm volatile("cp.async.commit_group;" ::: "memory")
#define CP_WAIT(n)  asm volatile("cp.async.wait_group %0;" :: "n"(n) : "memory")

// ------------------------- mask-mode detection ------------------------------
__global__ void detect_mask_kernel(const unsigned int* __restrict__ w, int nwords)
{
    __shared__ int sawFloat, sawMulti;
    if (threadIdx.x == 0) { sawFloat = 0; sawMulti = 0; }
    __syncthreads();
    for (int i = threadIdx.x; i < nwords; i += blockDim.x) {
        unsigned int v = w[i];
        if (v == 0x3F800000u) atomicOr(&sawFloat, 1);
        else if (v > 1u)      atomicOr(&sawMulti, 1);
    }
    __syncthreads();
    if (threadIdx.x == 0)
        g_mask_mode = sawFloat ? 2 : (sawMulti ? 0 : 1);
}

// ---------------- f32 -> f16 conversion of the 3 weight matrices ------------
__global__ void cvt3_kernel(const float4* __restrict__ w1, __half2* __restrict__ o1, int n1,
                            const float4* __restrict__ w2, __half2* __restrict__ o2, int n2,
                            const float4* __restrict__ w3, __half2* __restrict__ o3, int n3)
{
    const int total = n1 + n2 + n3;
    for (int i = blockIdx.x * 256 + threadIdx.x; i < total; i += gridDim.x * 256) {
        const float4* src; __half2* dst; int j = i;
        if (j < n1)            { src = w1; dst = o1; }
        else if ((j -= n1) < n2) { src = w2; dst = o2; }
        else                   { j -= n2; src = w3; dst = o3; }
        float4 v = src[j];
        dst[2 * j]     = __floats2half2_rn(v.x, v.y);
        dst[2 * j + 1] = __floats2half2_rn(v.z, v.w);
    }
}

// --------------- transpose+cvt: x f32 -> xh [C,E] f16 AND xTh [E,C] f16 -----
// (16,16) block, 64(e) x 32(c) tile, vectorized loads/stores.
__global__ void transpose_dual_kernel(const float* __restrict__ in,
                                      __half* __restrict__ xh,
                                      __half* __restrict__ xTh)
{
    __shared__ float t[32][68];          // [c][e], padded
    const long long boff = (long long)blockIdx.z * CDIM * EDIM;
    const int e0 = blockIdx.x * 64, c0 = blockIdx.y * 32;
    const int tx = threadIdx.x, ty = threadIdx.y;   // (16, 16)

    #pragma unroll
    for (int j = 0; j < 2; j++) {
        const int c = c0 + ty + j * 16;
        float4 v = *reinterpret_cast<const float4*>(
            in + boff + (long long)c * EDIM + e0 + 4 * tx);
        t[ty + j * 16][4 * tx + 0] = v.x;
        t[ty + j * 16][4 * tx + 1] = v.y;
        t[ty + j * 16][4 * tx + 2] = v.z;
        t[ty + j * 16][4 * tx + 3] = v.w;
        __half2 h0 = __floats2half2_rn(v.x, v.y);
        __half2 h1 = __floats2half2_rn(v.z, v.w);
        uint2 u;
        u.x = *reinterpret_cast<unsigned*>(&h0);
        u.y = *reinterpret_cast<unsigned*>(&h1);
        *reinterpret_cast<uint2*>(xh + boff + (long long)c * EDIM + e0 + 4 * tx) = u;
    }
    __syncthreads();
    #pragma unroll
    for (int j = 0; j < 4; j++) {
        const int er = ty + j * 16;      // e within tile (0..63)
        __half2 h = __floats2half2_rn(t[2 * tx][er], t[2 * tx + 1][er]);
        *reinterpret_cast<__half2*>(
            xTh + boff + (long long)(e0 + er) * CDIM + c0 + 2 * tx) = h;
    }
}

// ---------------------------------------------------------------------------
// Persistent FP16 mma.sync NT GEMM: C[m,n] = sum_k A[m,k]*B[n,k] (+f32 bias)
// Grid = 2*SMs persistent CTAs, grid-striding a flattened (op,batch,by,bx)
// tile list. Block tile 128x128, 128 thr, 4 warps (2x2, warp 64x64),
// K-chunk 64 (128B rows, XOR swizzle), cp.async 3-stage, ldmatrix.x4 with
// one-step register double-buffering.
// biasMode: 0=none, 1=col, 2=row. outMode: 0=f16, 1=f32, 2=f16*SCALE.
// ---------------------------------------------------------------------------
#define STAGE_BYTES 32768                 // A 16KB + B 16KB
#define NSTAGE 3
#define SMEM_DYN   (NSTAGE * STAGE_BYTES) // 96 KB

#define ATT_SCALE 0.022097086912079612f   // 1/sqrt(2048)

struct GOp {
    const __half* A; const __half* B; const float* bias; void* C;
    long long sA, sB, sC;
    int K, lda, ldb, ldc, biasMode, outMode, nbx, ntb /*nbx*nby*/, off;
};
struct GParams { GOp op[3]; int nops; int total; };

__device__ __forceinline__ void cp_tile_h(uint32_t base, const __half* g, int ld, int tid)
{
    #pragma unroll
    for (int l = 0; l < 8; l++) {
        int idx = tid + l * 128;          // 0..1023
        int r  = idx >> 3;                // 0..127
        int cb = (idx & 7) << 4;          // byte col 0..112
        uint32_t dst = base + r * 128 + (cb ^ ((r & 7) << 4));
        const __half* src = g + (long long)r * ld + (cb >> 1);
        asm volatile("cp.async.cg.shared.global [%0], [%1], 16;"
                     :: "r"(dst), "l"(src) : "memory");
    }
}

__global__ void __launch_bounds__(128, 2)
gemm_any(GParams P)
{
    extern __shared__ char sm[];
    const uint32_t smem0 = smem_u32(sm);

    const int tid  = threadIdx.x;
    const int lane = tid & 31;
    const int wid  = tid >> 5;
    const int wm   = (wid & 1) * 64;
    const int wn   = (wid >> 1) * 64;
    const int g    = lane >> 2;
    const int tc   = lane & 3;

    // ldmatrix per-lane address components
    const int arow = (lane & 15);
    const int akx  = (lane >> 4) << 4;
    const int brow = (lane & 7) + ((lane >> 4) & 1) * 8;
    const int bkx  = ((lane >> 3) & 1) << 4;

    for (int t = blockIdx.x; t < P.total; t += gridDim.x) {
        int oi = 0;
        if (P.nops > 1 && t >= P.op[1].off) oi = 1;
        if (P.nops > 2 && t >= P.op[2].off) oi = 2;
        const GOp o = P.op[oi];
        int rem = t - o.off;
        const int batch = rem / o.ntb;
        rem -= batch * o.ntb;
        const int bx = rem % o.nbx;
        const int by = rem / o.nbx;

        const __half* A = o.A + (long long)batch * o.sA + (long long)(by * 128) * o.lda;
        const __half* B = o.B + (long long)batch * o.sB + (long long)(bx * 128) * o.ldb;

        float acc[4][8][4];
        #pragma unroll
        for (int i = 0; i < 4; i++)
            #pragma unroll
            for (int j = 0; j < 8; j++)
                #pragma unroll
                for (int k = 0; k < 4; k++) acc[i][j][k] = 0.f;

        const int nk = o.K >> 6;          // K-chunks of 64

        __syncthreads();                  // smem stages free from previous tile
        cp_tile_h(smem0,         A, o.lda, tid);
        cp_tile_h(smem0 + 16384, B, o.ldb, tid);
        CP_COMMIT();
        cp_tile_h(smem0 + STAGE_BYTES,         A + 64, o.lda, tid);
        cp_tile_h(smem0 + STAGE_BYTES + 16384, B + 64, o.ldb, tid);
        CP_COMMIT();

        int s = 0;
        for (int i = 0; i < nk; i++) {
            if (i + 1 < nk) CP_WAIT(1); else CP_WAIT(0);
            __syncthreads();
            if (i + 2 < nk) {
                int s2 = s + 2; if (s2 >= NSTAGE) s2 -= NSTAGE;
                const uint32_t nb = smem0 + s2 * STAGE_BYTES;
                cp_tile_h(nb,         A + (i + 2) * 64, o.lda, tid);
                cp_tile_h(nb + 16384, B + (i + 2) * 64, o.ldb, tid);
                CP_COMMIT();
            }

            const uint32_t As = smem0 + s * STAGE_BYTES;
            const uint32_t Bs = As + 16384;

            unsigned a0[4][4], b0[4][4], a1[4][4], b1[4][4];
            #pragma unroll
            for (int mf = 0; mf < 4; mf++) {
                int r = wm + mf * 16 + arow;
                ldm_x4(a0[mf], As + r * 128 + ((0 + akx) ^ ((r & 7) << 4)));
            }
            #pragma unroll
            for (int p = 0; p < 4; p++) {
                int r = wn + p * 16 + brow;
                ldm_x4(b0[p], Bs + r * 128 + ((0 + bkx) ^ ((r & 7) << 4)));
            }
            #pragma unroll
            for (int ks = 0; ks < 4; ks++) {
                unsigned (&ac)[4][4] = (ks & 1) ? a1 : a0;
                unsigned (&bc)[4][4] = (ks & 1) ? b1 : b0;
                unsigned (&an)[4][4] = (ks & 1) ? a0 : a1;
                unsigned (&bn)[4][4] = (ks & 1) ? b0 : b1;
                if (ks < 3) {
                    const int kb = (ks + 1) * 32;
                    #pragma unroll
                    for (int mf = 0; mf < 4; mf++) {
                        int r = wm + mf * 16 + arow;
                        ldm_x4(an[mf], As + r * 128 + ((kb + akx) ^ ((r & 7) << 4)));
                    }
                    #pragma unroll
                    for (int p = 0; p < 4; p++) {
                        int r = wn + p * 16 + brow;
                        ldm_x4(bn[p], Bs + r * 128 + ((kb + bkx) ^ ((r & 7) << 4)));
                    }
                }
                #pragma unroll
                for (int mf = 0; mf < 4; mf++)
                    #pragma unroll
                    for (int p = 0; p < 4; p++) {
                        mma_f16(acc[mf][2 * p],     ac[mf], &bc[p][0]);
                        mma_f16(acc[mf][2 * p + 1], ac[mf], &bc[p][2]);
                    }
            }
            if (++s == NSTAGE) s = 0;
        }

        // ------------------------- epilogue ---------------------------------
        #pragma unroll
        for (int mf = 0; mf < 4; mf++) {
            #pragma unroll
            for (int nf = 0; nf < 8; nf++) {
                const int r0 = by * 128 + wm + mf * 16 + g;
                const int c  = bx * 128 + wn + nf * 8 + 2 * tc;
                float v0 = acc[mf][nf][0], v1 = acc[mf][nf][1];
                float v2 = acc[mf][nf][2], v3 = acc[mf][nf][3];
                if (o.biasMode == 1) {
                    const float b0 = o.bias[c], b1 = o.bias[c + 1];
                    v0 += b0; v1 += b1; v2 += b0; v3 += b1;
                } else if (o.biasMode == 2) {
                    const float br0 = o.bias[r0], br1 = o.bias[r0 + 8];
                    v0 += br0; v1 += br0; v2 += br1; v3 += br1;
                }
                if (o.outMode == 1) {
                    float* Cb = (float*)o.C + (long long)batch * o.sC;
                    *reinterpret_cast<float2*>(Cb + (long long)r0 * o.ldc + c)       = make_float2(v0, v1);
                    *reinterpret_cast<float2*>(Cb + (long long)(r0 + 8) * o.ldc + c) = make_float2(v2, v3);
                } else {
                    const float scl = (o.outMode == 2) ? ATT_SCALE : 1.f;
                    __half* Cb = (__half*)o.C + (long long)batch * o.sC;
                    *reinterpret_cast<__half2*>(Cb + (long long)r0 * o.ldc + c)       = __floats2half2_rn(v0 * scl, v1 * scl);
                    *reinterpret_cast<__half2*>(Cb + (long long)(r0 + 8) * o.ldc + c) = __floats2half2_rn(v2 * scl, v3 * scl);
                }
            }
        }
    }
}

// ------------------------- masked softmax over k -----------------------------
// Vectorized: thread t owns 8 contiguous elems; warp-shuffle reductions.
__global__ void softmax_kernel(const __half* __restrict__ lg,
                               __half* __restrict__ attn_h,
                               const void* __restrict__ mask_raw)
{
    const long long row = blockIdx.x;
    const int t = threadIdx.x, lane = t & 31, wid = t >> 5;
    const int mode = g_mask_mode;

    // logits: 8 contiguous halves per thread
    uint4 raw = reinterpret_cast<const uint4*>(lg + row * CDIM)[t];
    float v[8];
    {
        __half2 h0 = *reinterpret_cast<__half2*>(&raw.x);
        __half2 h1 = *reinterpret_cast<__half2*>(&raw.y);
        __half2 h2 = *reinterpret_cast<__half2*>(&raw.z);
        __half2 h3 = *reinterpret_cast<__half2*>(&raw.w);
        v[0] = __low2float(h0); v[1] = __high2float(h0);
        v[2] = __low2float(h1); v[3] = __high2float(h1);
        v[4] = __low2float(h2); v[5] = __high2float(h2);
        v[6] = __low2float(h3); v[7] = __high2float(h3);
    }

    // mask: bit i of msk = element masked
    unsigned msk = 0;
    if (mode == 0) {
        uint2 m = reinterpret_cast<const uint2*>(
            (const unsigned char*)mask_raw + row * CDIM)[t];
        #pragma unroll
        for (int i = 0; i < 4; i++) {
            if ((m.x >> (8 * i)) & 0xFF) msk |= 1u << i;
            if ((m.y >> (8 * i)) & 0xFF) msk |= 1u << (4 + i);
        }
    } else {
        const uint4* mw = reinterpret_cast<const uint4*>(mask_raw) + row * (CDIM / 4);
        uint4 a = mw[2 * t], b = mw[2 * t + 1];
        if (a.x) msk |= 1u;        if (a.y) msk |= 2u;
        if (a.z) msk |= 4u;        if (a.w) msk |= 8u;
        if (b.x) msk |= 16u;       if (b.y) msk |= 32u;
        if (b.z) msk |= 64u;       if (b.w) msk |= 128u;
    }

    float lmax = -INFINITY;
    #pragma unroll
    for (int i = 0; i < 8; i++) {
        if (msk & (1u << i)) v[i] = -INFINITY;
        lmax = fmaxf(lmax, v[i]);
    }
    #pragma unroll
    for (int o = 16; o > 0; o >>= 1)
        lmax = fmaxf(lmax, __shfl_xor_sync(0xFFFFFFFFu, lmax, o));

    __shared__ float smax[8], ssum[8];
    if (lane == 0) smax[wid] = lmax;
    __syncthreads();
    float rmax = smax[0];
    #pragma unroll
    for (int i = 1; i < 8; i++) rmax = fmaxf(rmax, smax[i]);

    float lsum = 0.f;
    #pragma unroll
    for (int i = 0; i < 8; i++) {
        v[i] = (msk & (1u << i)) ? 0.f : __expf(v[i] - rmax);
        lsum += v[i];
    }
    #pragma unroll
    for (int o = 16; o > 0; o >>= 1)
        lsum += __shfl_xor_sync(0xFFFFFFFFu, lsum, o);
    if (lane == 0) ssum[wid] = lsum;
    __syncthreads();
    float tot = 0.f;
    #pragma unroll
    for (int i = 0; i < 8; i++) tot += ssum[i];
    const float inv = 1.f / tot;

    uint4 outw;
    {
        __half2 h0 = __floats2half2_rn(v[0] * inv, v[1] * inv);
        __half2 h1 = __floats2half2_rn(v[2] * inv, v[3] * inv);
        __half2 h2 = __floats2half2_rn(v[4] * inv, v[5] * inv);
        __half2 h3 = __floats2half2_rn(v[6] * inv, v[7] * inv);
        outw.x = *reinterpret_cast<unsigned*>(&h0);
        outw.y = *reinterpret_cast<unsigned*>(&h1);
        outw.z = *reinterpret_cast<unsigned*>(&h2);
        outw.w = *reinterpret_cast<unsigned*>(&h3);
    }
    reinterpret_cast<uint4*>(attn_h + row * CDIM)[t] = outw;
}

// ---------------------------------------------------------------------------
extern "C" void kernel_launch(void* const* d_in, const int* in_sizes, int n_in,
                              void* d_out, int out_size)
{
    const float* x     = (const float*)d_in[0];   // [B,C,E]
    const float* fc_w  = (const float*)d_in[1];   // [E,E]
    const float* fc_b  = (const float*)d_in[2];   // [E]
    const float* alt_w = (const float*)d_in[3];   // [C,C]
    const float* alt_b = (const float*)d_in[4];   // [C]
    const float* v_w   = (const float*)d_in[5];   // [E,E]
    const float* v_b   = (const float*)d_in[6];   // [E]
    const void*  mask  = d_in[7];                 // [B,C,C] bool (encoding detected)
    float* out = (float*)d_out;                   // [B,C,E]

    __half *xh, *xTh, *yh, *zh, *vxTh, *fwh, *vwh, *awh, *lgh, *attnh;
    cudaGetSymbolAddress((void**)&xh,    g_xh);
    cudaGetSymbolAddress((void**)&xTh,   g_xTh);
    cudaGetSymbolAddress((void**)&yh,    g_yh);
    cudaGetSymbolAddress((void**)&zh,    g_zh);
    cudaGetSymbolAddress((void**)&vxTh,  g_vxTh);
    cudaGetSymbolAddress((void**)&fwh,   g_fwh);
    cudaGetSymbolAddress((void**)&vwh,   g_vwh);
    cudaGetSymbolAddress((void**)&awh,   g_awh);
    cudaGetSymbolAddress((void**)&lgh,   g_lgh);
    cudaGetSymbolAddress((void**)&attnh, g_attnh);

    cudaFuncSetAttribute(gemm_any, cudaFuncAttributeMaxDynamicSharedMemorySize, SMEM_DYN);

    int smCount = 148;
    {
        int dev = 0;
        cudaGetDevice(&dev);
        cudaDeviceGetAttribute(&smCount, cudaDevAttrMultiProcessorCount, dev);
    }
    const int gridP = smCount * 2;       // persistent grid (2 CTAs/SM resident)

    const long long sCE = (long long)CDIM * EDIM;
    const long long sCC = (long long)CDIM * CDIM;

    // 0) mask encoding + fp16 conversions (one launch for all 3 weights)
    detect_mask_kernel<<<1, 256>>>((const unsigned int*)mask, 16384);
    cvt3_kernel<<<1024, 256>>>(
        (const float4*)fc_w,  (__half2*)fwh, (EDIM * EDIM) / 4,
        (const float4*)v_w,   (__half2*)vwh, (EDIM * EDIM) / 4,
        (const float4*)alt_w, (__half2*)awh, (CDIM * CDIM) / 4);
    transpose_dual_kernel<<<dim3(EDIM / 64, CDIM / 32, BATCH), dim3(16, 16)>>>(x, xh, xTh);

    // 1-3) merged independent GEMMs, persistent grid (1536 tiles)
    //      z (K=2048, heavy) FIRST so heavy tiles spread evenly across CTAs.
    {
        GParams P; P.nops = 3;
        P.op[0] = { awh, xTh, alt_b, zh,   0,   sCE, sCE, CDIM, CDIM, CDIM, EDIM, 2, 0, EDIM / 128, (EDIM / 128) * (CDIM / 128), 0 };
        P.op[1] = { xh,  fwh, fc_b,  yh,   sCE, 0,   sCE, EDIM, EDIM, EDIM, EDIM, 1, 0, EDIM / 128, (EDIM / 128) * (CDIM / 128), 512 };
        P.op[2] = { vwh, xh,  v_b,   vxTh, 0,   sCE, sCE, EDIM, EDIM, EDIM, CDIM, 2, 0, CDIM / 128, (CDIM / 128) * (EDIM / 128), 1024 };
        P.total = 1536;
        gemm_any<<<gridP, 128, SMEM_DYN>>>(P);
    }

    // 4) logits[c,k] = (sum_e y[c,e]*z[k,e]) * 1/sqrt(C)  -> f16  (1024 tiles)
    {
        GParams P; P.nops = 1;
        P.op[0] = { yh, zh, nullptr, lgh, sCE, sCE, sCC, EDIM, EDIM, EDIM, CDIM, 0, 2, CDIM / 128, (CDIM / 128) * (CDIM / 128), 0 };
        P.total = 1024;
        gemm_any<<<gridP, 128, SMEM_DYN>>>(P);
    }

    // 5) masked softmax over k -> fp16 weights
    softmax_kernel<<<BATCH * CDIM, 256>>>(lgh, attnh, mask);

    // 6) out[c,e] = sum_k attn[c,k]*vxT[e,k]  (f32 out, 512 tiles)
    {
        GParams P; P.nops = 1;
        P.op[0] = { attnh, vxTh, nullptr, out, sCC, sCE, sCE, CDIM, CDIM, CDIM, EDIM, 0, 1, EDIM / 128, (EDIM / 128) * (CDIM / 128), 0 };
        P.total = 512;
        gemm_any<<<gridP, 128, SMEM_DYN>>>(P);
    }
}

// round 13
// speedup vs baseline: 2.1123x; 1.0095x over previous
#include <cuda_runtime.h>
#include <cuda_fp16.h>
#include <cstdint>
#include <math.h>

#define BATCH 4
#define CDIM  2048
#define EDIM  1024

// ------------------------- scratch (__device__ globals) ---------------------
__device__ __half g_xh  [(size_t)BATCH * CDIM * EDIM];  // x    [b,C,E] fp16
__device__ __half g_xTh [(size_t)BATCH * CDIM * EDIM];  // xT   [b,E,C] fp16
__device__ __half g_yh  [(size_t)BATCH * CDIM * EDIM];  // y    [b,C,E] fp16
__device__ __half g_zh  [(size_t)BATCH * CDIM * EDIM];  // z    [b,C,E] fp16
__device__ __half g_vxTh[(size_t)BATCH * CDIM * EDIM];  // vxT  [b,E,C] fp16
__device__ __half g_fwh [(size_t)EDIM * EDIM];          // fp16 weights
__device__ __half g_vwh [(size_t)EDIM * EDIM];
__device__ __half g_awh [(size_t)CDIM * CDIM];
__device__ __half g_lgh  [(size_t)BATCH * CDIM * CDIM]; // attn logits*scale f16
__device__ __half g_attnh[(size_t)BATCH * CDIM * CDIM]; // attn weights fp16
__device__ int    g_mask_mode;                          // 0=u8, 1=i32(words), 2=f32

// ------------------------- helpers ------------------------------------------
__device__ __forceinline__ uint32_t smem_u32(const void* p) {
    uint32_t a;
    asm("{ .reg .u64 t; cvta.to.shared.u64 t, %1; cvt.u32.u64 %0, t; }"
        : "=r"(a) : "l"(p));
    return a;
}
__device__ __forceinline__ void ldm_x4(unsigned* r, uint32_t addr) {
    asm volatile("ldmatrix.sync.aligned.m8n8.x4.shared.b16 {%0,%1,%2,%3}, [%4];"
                 : "=r"(r[0]), "=r"(r[1]), "=r"(r[2]), "=r"(r[3]) : "r"(addr));
}
__device__ __forceinline__ void mma_f16(float* c, const unsigned* a, const unsigned* b) {
    asm volatile(
        "mma.sync.aligned.m16n8k16.row.col.f32.f16.f16.f32 "
        "{%0,%1,%2,%3}, {%4,%5,%6,%7}, {%8,%9}, {%0,%1,%2,%3};"
        : "+f"(c[0]), "+f"(c[1]), "+f"(c[2]), "+f"(c[3])
        : "r"(a[0]), "r"(a[1]), "r"(a[2]), "r"(a[3]), "r"(b[0]), "r"(b[1]));
}
#define CP_COMMIT() asm volatile("cp.async.commit_group;" ::: "memory")
#define CP_WAIT(n)  asm volatile("cp.async.wait_group %0;" :: "n"(n) : "memory")

// ---- f32 -> f16 conversion of the 3 weight matrices + mask-mode detection ---
__global__ void cvt3_kernel(const float4* __restrict__ w1, __half2* __restrict__ o1, int n1,
                            const float4* __restrict__ w2, __half2* __restrict__ o2, int n2,
                            const float4* __restrict__ w3, __half2* __restrict__ o3, int n3,
                            const unsigned int* __restrict__ maskw)
{
    // block 0 additionally detects mask encoding (16K words is conclusive)
    if (blockIdx.x == 0) {
        __shared__ int sawFloat, sawMulti;
        if (threadIdx.x == 0) { sawFloat = 0; sawMulti = 0; }
        __syncthreads();
        for (int i = threadIdx.x; i < 16384; i += blockDim.x) {
            unsigned int v = maskw[i];
            if (v == 0x3F800000u) atomicOr(&sawFloat, 1);
            else if (v > 1u)      atomicOr(&sawMulti, 1);
        }
        __syncthreads();
        if (threadIdx.x == 0)
            g_mask_mode = sawFloat ? 2 : (sawMulti ? 0 : 1);
    }

    const int total = n1 + n2 + n3;
    for (int i = blockIdx.x * 256 + threadIdx.x; i < total; i += gridDim.x * 256) {
        const float4* src; __half2* dst; int j = i;
        if (j < n1)              { src = w1; dst = o1; }
        else if ((j -= n1) < n2) { src = w2; dst = o2; }
        else                     { j -= n2; src = w3; dst = o3; }
        float4 v = src[j];
        dst[2 * j]     = __floats2half2_rn(v.x, v.y);
        dst[2 * j + 1] = __floats2half2_rn(v.z, v.w);
    }
}

// --------------- transpose+cvt: x f32 -> xh [C,E] f16 AND xTh [E,C] f16 -----
// (16,16) block, 64(e) x 32(c) tile, vectorized loads/stores.
__global__ void transpose_dual_kernel(const float* __restrict__ in,
                                      __half* __restrict__ xh,
                                      __half* __restrict__ xTh)
{
    __shared__ float t[32][68];          // [c][e], padded
    const long long boff = (long long)blockIdx.z * CDIM * EDIM;
    const int e0 = blockIdx.x * 64, c0 = blockIdx.y * 32;
    const int tx = threadIdx.x, ty = threadIdx.y;   // (16, 16)

    #pragma unroll
    for (int j = 0; j < 2; j++) {
        const int c = c0 + ty + j * 16;
        float4 v = *reinterpret_cast<const float4*>(
            in + boff + (long long)c * EDIM + e0 + 4 * tx);
        t[ty + j * 16][4 * tx + 0] = v.x;
        t[ty + j * 16][4 * tx + 1] = v.y;
        t[ty + j * 16][4 * tx + 2] = v.z;
        t[ty + j * 16][4 * tx + 3] = v.w;
        __half2 h0 = __floats2half2_rn(v.x, v.y);
        __half2 h1 = __floats2half2_rn(v.z, v.w);
        uint2 u;
        u.x = *reinterpret_cast<unsigned*>(&h0);
        u.y = *reinterpret_cast<unsigned*>(&h1);
        *reinterpret_cast<uint2*>(xh + boff + (long long)c * EDIM + e0 + 4 * tx) = u;
    }
    __syncthreads();
    #pragma unroll
    for (int j = 0; j < 4; j++) {
        const int er = ty + j * 16;      // e within tile (0..63)
        __half2 h = __floats2half2_rn(t[2 * tx][er], t[2 * tx + 1][er]);
        *reinterpret_cast<__half2*>(
            xTh + boff + (long long)(e0 + er) * CDIM + c0 + 2 * tx) = h;
    }
}

// ---------------------------------------------------------------------------
// Persistent FP16 mma.sync NT GEMM: C[m,n] = sum_k A[m,k]*B[n,k] (+f32 bias)
// Grid = 2*SMs persistent CTAs, grid-striding a flattened (op,batch,by,bx)
// tile list. Block tile 128x128, 128 thr, 4 warps (2x2, warp 64x64),
// K-chunk 64 (128B rows, XOR swizzle), cp.async 3-stage, ldmatrix.x4 with
// one-step register double-buffering.
// biasMode: 0=none, 1=col, 2=row. outMode: 0=f16, 1=f32, 2=f16*SCALE.
// ---------------------------------------------------------------------------
#define STAGE_BYTES 32768                 // A 16KB + B 16KB
#define NSTAGE 3
#define SMEM_DYN   (NSTAGE * STAGE_BYTES) // 96 KB

#define ATT_SCALE 0.022097086912079612f   // 1/sqrt(2048)

struct GOp {
    const __half* A; const __half* B; const float* bias; void* C;
    long long sA, sB, sC;
    int K, lda, ldb, ldc, biasMode, outMode, nbx, ntb /*nbx*nby*/, off;
};
struct GParams { GOp op[3]; int nops; int total; };

__device__ __forceinline__ void cp_tile_h(uint32_t base, const __half* g, int ld, int tid)
{
    #pragma unroll
    for (int l = 0; l < 8; l++) {
        int idx = tid + l * 128;          // 0..1023
        int r  = idx >> 3;                // 0..127
        int cb = (idx & 7) << 4;          // byte col 0..112
        uint32_t dst = base + r * 128 + (cb ^ ((r & 7) << 4));
        const __half* src = g + (long long)r * ld + (cb >> 1);
        asm volatile("cp.async.cg.shared.global [%0], [%1], 16;"
                     :: "r"(dst), "l"(src) : "memory");
    }
}

__global__ void __launch_bounds__(128, 2)
gemm_any(GParams P)
{
    extern __shared__ char sm[];
    const uint32_t smem0 = smem_u32(sm);

    const int tid  = threadIdx.x;
    const int lane = tid & 31;
    const int wid  = tid >> 5;
    const int wm   = (wid & 1) * 64;
    const int wn   = (wid >> 1) * 64;
    const int g    = lane >> 2;
    const int tc   = lane & 3;

    // ldmatrix per-lane address components
    const int arow = (lane & 15);
    const int akx  = (lane >> 4) << 4;
    const int brow = (lane & 7) + ((lane >> 4) & 1) * 8;
    const int bkx  = ((lane >> 3) & 1) << 4;

    for (int t = blockIdx.x; t < P.total; t += gridDim.x) {
        int oi = 0;
        if (P.nops > 1 && t >= P.op[1].off) oi = 1;
        if (P.nops > 2 && t >= P.op[2].off) oi = 2;
        const GOp o = P.op[oi];
        int rem = t - o.off;
        const int batch = rem / o.ntb;
        rem -= batch * o.ntb;
        const int bx = rem % o.nbx;
        const int by = rem / o.nbx;

        const __half* A = o.A + (long long)batch * o.sA + (long long)(by * 128) * o.lda;
        const __half* B = o.B + (long long)batch * o.sB + (long long)(bx * 128) * o.ldb;

        float acc[4][8][4];
        #pragma unroll
        for (int i = 0; i < 4; i++)
            #pragma unroll
            for (int j = 0; j < 8; j++)
                #pragma unroll
                for (int k = 0; k < 4; k++) acc[i][j][k] = 0.f;

        const int nk = o.K >> 6;          // K-chunks of 64

        __syncthreads();                  // smem stages free from previous tile
        cp_tile_h(smem0,         A, o.lda, tid);
        cp_tile_h(smem0 + 16384, B, o.ldb, tid);
        CP_COMMIT();
        cp_tile_h(smem0 + STAGE_BYTES,         A + 64, o.lda, tid);
        cp_tile_h(smem0 + STAGE_BYTES + 16384, B + 64, o.ldb, tid);
        CP_COMMIT();

        int s = 0;
        for (int i = 0; i < nk; i++) {
            if (i + 1 < nk) CP_WAIT(1); else CP_WAIT(0);
            __syncthreads();
            if (i + 2 < nk) {
                int s2 = s + 2; if (s2 >= NSTAGE) s2 -= NSTAGE;
                const uint32_t nb = smem0 + s2 * STAGE_BYTES;
                cp_tile_h(nb,         A + (i + 2) * 64, o.lda, tid);
                cp_tile_h(nb + 16384, B + (i + 2) * 64, o.ldb, tid);
                CP_COMMIT();
            }

            const uint32_t As = smem0 + s * STAGE_BYTES;
            const uint32_t Bs = As + 16384;

            unsigned a0[4][4], b0[4][4], a1[4][4], b1[4][4];
            #pragma unroll
            for (int mf = 0; mf < 4; mf++) {
                int r = wm + mf * 16 + arow;
                ldm_x4(a0[mf], As + r * 128 + ((0 + akx) ^ ((r & 7) << 4)));
            }
            #pragma unroll
            for (int p = 0; p < 4; p++) {
                int r = wn + p * 16 + brow;
                ldm_x4(b0[p], Bs + r * 128 + ((0 + bkx) ^ ((r & 7) << 4)));
            }
            #pragma unroll
            for (int ks = 0; ks < 4; ks++) {
                unsigned (&ac)[4][4] = (ks & 1) ? a1 : a0;
                unsigned (&bc)[4][4] = (ks & 1) ? b1 : b0;
                unsigned (&an)[4][4] = (ks & 1) ? a0 : a1;
                unsigned (&bn)[4][4] = (ks & 1) ? b0 : b1;
                if (ks < 3) {
                    const int kb = (ks + 1) * 32;
                    #pragma unroll
                    for (int mf = 0; mf < 4; mf++) {
                        int r = wm + mf * 16 + arow;
                        ldm_x4(an[mf], As + r * 128 + ((kb + akx) ^ ((r & 7) << 4)));
                    }
                    #pragma unroll
                    for (int p = 0; p < 4; p++) {
                        int r = wn + p * 16 + brow;
                        ldm_x4(bn[p], Bs + r * 128 + ((kb + bkx) ^ ((r & 7) << 4)));
                    }
                }
                #pragma unroll
                for (int mf = 0; mf < 4; mf++)
                    #pragma unroll
                    for (int p = 0; p < 4; p++) {
                        mma_f16(acc[mf][2 * p],     ac[mf], &bc[p][0]);
                        mma_f16(acc[mf][2 * p + 1], ac[mf], &bc[p][2]);
                    }
            }
            if (++s == NSTAGE) s = 0;
        }

        // ------------------------- epilogue ---------------------------------
        #pragma unroll
        for (int mf = 0; mf < 4; mf++) {
            #pragma unroll
            for (int nf = 0; nf < 8; nf++) {
                const int r0 = by * 128 + wm + mf * 16 + g;
                const int c  = bx * 128 + wn + nf * 8 + 2 * tc;
                float v0 = acc[mf][nf][0], v1 = acc[mf][nf][1];
                float v2 = acc[mf][nf][2], v3 = acc[mf][nf][3];
                if (o.biasMode == 1) {
                    const float b0 = o.bias[c], b1 = o.bias[c + 1];
                    v0 += b0; v1 += b1; v2 += b0; v3 += b1;
                } else if (o.biasMode == 2) {
                    const float br0 = o.bias[r0], br1 = o.bias[r0 + 8];
                    v0 += br0; v1 += br0; v2 += br1; v3 += br1;
                }
                if (o.outMode == 1) {
                    float* Cb = (float*)o.C + (long long)batch * o.sC;
                    *reinterpret_cast<float2*>(Cb + (long long)r0 * o.ldc + c)       = make_float2(v0, v1);
                    *reinterpret_cast<float2*>(Cb + (long long)(r0 + 8) * o.ldc + c) = make_float2(v2, v3);
                } else {
                    const float scl = (o.outMode == 2) ? ATT_SCALE : 1.f;
                    __half* Cb = (__half*)o.C + (long long)batch * o.sC;
                    *reinterpret_cast<__half2*>(Cb + (long long)r0 * o.ldc + c)       = __floats2half2_rn(v0 * scl, v1 * scl);
                    *reinterpret_cast<__half2*>(Cb + (long long)(r0 + 8) * o.ldc + c) = __floats2half2_rn(v2 * scl, v3 * scl);
                }
            }
        }
    }
}

// ------------------------- masked softmax over k -----------------------------
// Vectorized: thread t owns 8 contiguous elems; warp-shuffle reductions.
__global__ void softmax_kernel(const __half* __restrict__ lg,
                               __half* __restrict__ attn_h,
                               const void* __restrict__ mask_raw)
{
    const long long row = blockIdx.x;
    const int t = threadIdx.x, lane = t & 31, wid = t >> 5;
    const int mode = g_mask_mode;

    // logits: 8 contiguous halves per thread
    uint4 raw = reinterpret_cast<const uint4*>(lg + row * CDIM)[t];
    float v[8];
    {
        __half2 h0 = *reinterpret_cast<__half2*>(&raw.x);
        __half2 h1 = *reinterpret_cast<__half2*>(&raw.y);
        __half2 h2 = *reinterpret_cast<__half2*>(&raw.z);
        __half2 h3 = *reinterpret_cast<__half2*>(&raw.w);
        v[0] = __low2float(h0); v[1] = __high2float(h0);
        v[2] = __low2float(h1); v[3] = __high2float(h1);
        v[4] = __low2float(h2); v[5] = __high2float(h2);
        v[6] = __low2float(h3); v[7] = __high2float(h3);
    }

    // mask: bit i of msk = element masked
    unsigned msk = 0;
    if (mode == 0) {
        uint2 m = reinterpret_cast<const uint2*>(
            (const unsigned char*)mask_raw + row * CDIM)[t];
        #pragma unroll
        for (int i = 0; i < 4; i++) {
            if ((m.x >> (8 * i)) & 0xFF) msk |= 1u << i;
            if ((m.y >> (8 * i)) & 0xFF) msk |= 1u << (4 + i);
        }
    } else {
        const uint4* mw = reinterpret_cast<const uint4*>(mask_raw) + row * (CDIM / 4);
        uint4 a = mw[2 * t], b = mw[2 * t + 1];
        if (a.x) msk |= 1u;        if (a.y) msk |= 2u;
        if (a.z) msk |= 4u;        if (a.w) msk |= 8u;
        if (b.x) msk |= 16u;       if (b.y) msk |= 32u;
        if (b.z) msk |= 64u;       if (b.w) msk |= 128u;
    }

    float lmax = -INFINITY;
    #pragma unroll
    for (int i = 0; i < 8; i++) {
        if (msk & (1u << i)) v[i] = -INFINITY;
        lmax = fmaxf(lmax, v[i]);
    }
    #pragma unroll
    for (int o = 16; o > 0; o >>= 1)
        lmax = fmaxf(lmax, __shfl_xor_sync(0xFFFFFFFFu, lmax, o));

    __shared__ float smax[8], ssum[8];
    if (lane == 0) smax[wid] = lmax;
    __syncthreads();
    float rmax = smax[0];
    #pragma unroll
    for (int i = 1; i < 8; i++) rmax = fmaxf(rmax, smax[i]);

    float lsum = 0.f;
    #pragma unroll
    for (int i = 0; i < 8; i++) {
        v[i] = (msk & (1u << i)) ? 0.f : __expf(v[i] - rmax);
        lsum += v[i];
    }
    #pragma unroll
    for (int o = 16; o > 0; o >>= 1)
        lsum += __shfl_xor_sync(0xFFFFFFFFu, lsum, o);
    if (lane == 0) ssum[wid] = lsum;
    __syncthreads();
    float tot = 0.f;
    #pragma unroll
    for (int i = 0; i < 8; i++) tot += ssum[i];
    const float inv = 1.f / tot;

    uint4 outw;
    {
        __half2 h0 = __floats2half2_rn(v[0] * inv, v[1] * inv);
        __half2 h1 = __floats2half2_rn(v[2] * inv, v[3] * inv);
        __half2 h2 = __floats2half2_rn(v[4] * inv, v[5] * inv);
        __half2 h3 = __floats2half2_rn(v[6] * inv, v[7] * inv);
        outw.x = *reinterpret_cast<unsigned*>(&h0);
        outw.y = *reinterpret_cast<unsigned*>(&h1);
        outw.z = *reinterpret_cast<unsigned*>(&h2);
        outw.w = *reinterpret_cast<unsigned*>(&h3);
    }
    reinterpret_cast<uint4*>(attn_h + row * CDIM)[t] = outw;
}

// ---------------------------------------------------------------------------
extern "C" void kernel_launch(void* const* d_in, const int* in_sizes, int n_in,
                              void* d_out, int out_size)
{
    const float* x     = (const float*)d_in[0];   // [B,C,E]
    const float* fc_w  = (const float*)d_in[1];   // [E,E]
    const float* fc_b  = (const float*)d_in[2];   // [E]
    const float* alt_w = (const float*)d_in[3];   // [C,C]
    const float* alt_b = (const float*)d_in[4];   // [C]
    const float* v_w   = (const float*)d_in[5];   // [E,E]
    const float* v_b   = (const float*)d_in[6];   // [E]
    const void*  mask  = d_in[7];                 // [B,C,C] bool (encoding detected)
    float* out = (float*)d_out;                   // [B,C,E]

    __half *xh, *xTh, *yh, *zh, *vxTh, *fwh, *vwh, *awh, *lgh, *attnh;
    cudaGetSymbolAddress((void**)&xh,    g_xh);
    cudaGetSymbolAddress((void**)&xTh,   g_xTh);
    cudaGetSymbolAddress((void**)&yh,    g_yh);
    cudaGetSymbolAddress((void**)&zh,    g_zh);
    cudaGetSymbolAddress((void**)&vxTh,  g_vxTh);
    cudaGetSymbolAddress((void**)&fwh,   g_fwh);
    cudaGetSymbolAddress((void**)&vwh,   g_vwh);
    cudaGetSymbolAddress((void**)&awh,   g_awh);
    cudaGetSymbolAddress((void**)&lgh,   g_lgh);
    cudaGetSymbolAddress((void**)&attnh, g_attnh);

    cudaFuncSetAttribute(gemm_any, cudaFuncAttributeMaxDynamicSharedMemorySize, SMEM_DYN);

    int smCount = 148;
    {
        int dev = 0;
        cudaGetDevice(&dev);
        cudaDeviceGetAttribute(&smCount, cudaDevAttrMultiProcessorCount, dev);
    }
    const int gridP = smCount * 2;       // persistent grid (2 CTAs/SM resident)

    const long long sCE = (long long)CDIM * EDIM;
    const long long sCC = (long long)CDIM * CDIM;

    // 0) fp16 weight conversions + mask-mode detection (single launch)
    cvt3_kernel<<<1024, 256>>>(
        (const float4*)fc_w,  (__half2*)fwh, (EDIM * EDIM) / 4,
        (const float4*)v_w,   (__half2*)vwh, (EDIM * EDIM) / 4,
        (const float4*)alt_w, (__half2*)awh, (CDIM * CDIM) / 4,
        (const unsigned int*)mask);
    transpose_dual_kernel<<<dim3(EDIM / 64, CDIM / 32, BATCH), dim3(16, 16)>>>(x, xh, xTh);

    // 1-3) merged independent GEMMs, persistent grid (1536 tiles), R10 order
    {
        GParams P; P.nops = 3;
        P.op[0] = { xh,  fwh, fc_b,  yh,   sCE, 0,   sCE, EDIM, EDIM, EDIM, EDIM, 1, 0, EDIM / 128, (EDIM / 128) * (CDIM / 128), 0 };
        P.op[1] = { vwh, xh,  v_b,   vxTh, 0,   sCE, sCE, EDIM, EDIM, EDIM, CDIM, 2, 0, CDIM / 128, (CDIM / 128) * (EDIM / 128), 512 };
        P.op[2] = { awh, xTh, alt_b, zh,   0,   sCE, sCE, CDIM, CDIM, CDIM, EDIM, 2, 0, EDIM / 128, (EDIM / 128) * (CDIM / 128), 1024 };
        P.total = 1536;
        gemm_any<<<gridP, 128, SMEM_DYN>>>(P);
    }

    // 4) logits[c,k] = (sum_e y[c,e]*z[k,e]) * 1/sqrt(C)  -> f16  (1024 tiles)
    {
        GParams P; P.nops = 1;
        P.op[0] = { yh, zh, nullptr, lgh, sCE, sCE, sCC, EDIM, EDIM, EDIM, CDIM, 0, 2, CDIM / 128, (CDIM / 128) * (CDIM / 128), 0 };
        P.total = 1024;
        gemm_any<<<gridP, 128, SMEM_DYN>>>(P);
    }

    // 5) masked softmax over k -> fp16 weights
    softmax_kernel<<<BATCH * CDIM, 256>>>(lgh, attnh, mask);

    // 6) out[c,e] = sum_k attn[c,k]*vxT[e,k]  (f32 out, 512 tiles)
    {
        GParams P; P.nops = 1;
        P.op[0] = { attnh, vxTh, nullptr, out, sCC, sCE, sCE, CDIM, CDIM, CDIM, EDIM, 0, 1, EDIM / 128, (EDIM / 128) * (CDIM / 128), 0 };
        P.total = 512;
        gemm_any<<<gridP, 128, SMEM_DYN>>>(P);
    }
}

// round 14
// speedup vs baseline: 2.1566x; 1.0210x over previous
#include <cuda_runtime.h>
#include <cuda_fp16.h>
#include <cstdint>
#include <math.h>

#define BATCH 4
#define CDIM  2048
#define EDIM  1024

// ------------------------- scratch (__device__ globals) ---------------------
__device__ __half g_xh  [(size_t)BATCH * CDIM * EDIM];  // x    [b,C,E] fp16
__device__ __half g_xTh [(size_t)BATCH * CDIM * EDIM];  // xT   [b,E,C] fp16
__device__ __half g_yh  [(size_t)BATCH * CDIM * EDIM];  // y    [b,C,E] fp16
__device__ __half g_zh  [(size_t)BATCH * CDIM * EDIM];  // z    [b,C,E] fp16
__device__ __half g_vxTh[(size_t)BATCH * CDIM * EDIM];  // vxT  [b,E,C] fp16
__device__ __half g_fwh [(size_t)EDIM * EDIM];          // fp16 weights
__device__ __half g_vwh [(size_t)EDIM * EDIM];
__device__ __half g_awh [(size_t)CDIM * CDIM];
__device__ __half g_lgh  [(size_t)BATCH * CDIM * CDIM]; // attn logits*scale f16
__device__ __half g_attnh[(size_t)BATCH * CDIM * CDIM]; // attn weights fp16
__device__ int    g_mask_mode;                          // 0=u8, 1=i32(words), 2=f32

// ------------------------- helpers ------------------------------------------
__device__ __forceinline__ uint32_t smem_u32(const void* p) {
    uint32_t a;
    asm("{ .reg .u64 t; cvta.to.shared.u64 t, %1; cvt.u32.u64 %0, t; }"
        : "=r"(a) : "l"(p));
    return a;
}
__device__ __forceinline__ void ldm_x4(unsigned* r, uint32_t addr) {
    asm volatile("ldmatrix.sync.aligned.m8n8.x4.shared.b16 {%0,%1,%2,%3}, [%4];"
                 : "=r"(r[0]), "=r"(r[1]), "=r"(r[2]), "=r"(r[3]) : "r"(addr));
}
__device__ __forceinline__ void mma_f16(float* c, const unsigned* a, const unsigned* b) {
    asm volatile(
        "mma.sync.aligned.m16n8k16.row.col.f32.f16.f16.f32 "
        "{%0,%1,%2,%3}, {%4,%5,%6,%7}, {%8,%9}, {%0,%1,%2,%3};"
        : "+f"(c[0]), "+f"(c[1]), "+f"(c[2]), "+f"(c[3])
        : "r"(a[0]), "r"(a[1]), "r"(a[2]), "r"(a[3]), "r"(b[0]), "r"(b[1]));
}
#define CP_COMMIT() asm volatile("cp.async.commit_group;" ::: "memory")
#define CP_WAIT(n)  asm volatile("cp.async.wait_group %0;" :: "n"(n) : "memory")

// ---------------------------------------------------------------------------
// prep_kernel: one launch doing
//   blocks [0, NTRB)       : dual transpose+cvt of x -> xh [C,E], xTh [E,C]
//   blocks [NTRB, NTRB+1024): f32->f16 cvt of the 3 weight matrices
//   block NTRB additionally: mask-mode detection
// ---------------------------------------------------------------------------
#define NTRB ((EDIM / 64) * (CDIM / 32) * BATCH)   // 4096 transpose blocks

__global__ void prep_kernel(const float* __restrict__ x,
                            __half* __restrict__ xh, __half* __restrict__ xTh,
                            const float4* __restrict__ w1, __half2* __restrict__ o1, int n1,
                            const float4* __restrict__ w2, __half2* __restrict__ o2, int n2,
                            const float4* __restrict__ w3, __half2* __restrict__ o3, int n3,
                            const unsigned int* __restrict__ maskw)
{
    __shared__ float t[32][68];
    if (blockIdx.x < NTRB) {
        const int tb = blockIdx.x;
        const int e0 = (tb & 15) * 64;
        const int c0 = ((tb >> 4) & 63) * 32;
        const int b  = tb >> 10;
        const long long boff = (long long)b * CDIM * EDIM;
        const int tx = threadIdx.x & 15, ty = threadIdx.x >> 4;

        #pragma unroll
        for (int j = 0; j < 2; j++) {
            const int c = c0 + ty + j * 16;
            float4 v = *reinterpret_cast<const float4*>(
                x + boff + (long long)c * EDIM + e0 + 4 * tx);
            t[ty + j * 16][4 * tx + 0] = v.x;
            t[ty + j * 16][4 * tx + 1] = v.y;
            t[ty + j * 16][4 * tx + 2] = v.z;
            t[ty + j * 16][4 * tx + 3] = v.w;
            __half2 h0 = __floats2half2_rn(v.x, v.y);
            __half2 h1 = __floats2half2_rn(v.z, v.w);
            uint2 u;
            u.x = *reinterpret_cast<unsigned*>(&h0);
            u.y = *reinterpret_cast<unsigned*>(&h1);
            *reinterpret_cast<uint2*>(xh + boff + (long long)c * EDIM + e0 + 4 * tx) = u;
        }
        __syncthreads();
        #pragma unroll
        for (int j = 0; j < 4; j++) {
            const int er = ty + j * 16;
            __half2 h = __floats2half2_rn(t[2 * tx][er], t[2 * tx + 1][er]);
            *reinterpret_cast<__half2*>(
                xTh + boff + (long long)(e0 + er) * CDIM + c0 + 2 * tx) = h;
        }
    } else {
        if (blockIdx.x == NTRB) {            // mask-mode detection
            __shared__ int sawFloat, sawMulti;
            if (threadIdx.x == 0) { sawFloat = 0; sawMulti = 0; }
            __syncthreads();
            for (int i = threadIdx.x; i < 16384; i += blockDim.x) {
                unsigned int v = maskw[i];
                if (v == 0x3F800000u) atomicOr(&sawFloat, 1);
                else if (v > 1u)      atomicOr(&sawMulti, 1);
            }
            __syncthreads();
            if (threadIdx.x == 0)
                g_mask_mode = sawFloat ? 2 : (sawMulti ? 0 : 1);
        }
        const int total = n1 + n2 + n3;
        for (int i = (blockIdx.x - NTRB) * 256 + threadIdx.x; i < total; i += 1024 * 256) {
            const float4* src; __half2* dst; int j = i;
            if (j < n1)              { src = w1; dst = o1; }
            else if ((j -= n1) < n2) { src = w2; dst = o2; }
            else                     { j -= n2; src = w3; dst = o3; }
            float4 v = src[j];
            dst[2 * j]     = __floats2half2_rn(v.x, v.y);
            dst[2 * j + 1] = __floats2half2_rn(v.z, v.w);
        }
    }
}

// ---------------------------------------------------------------------------
// Persistent FP16 mma.sync NT GEMM: C[m,n] = sum_k A[m,k]*B[n,k] (+f32 bias)
// Grid = 2*SMs persistent CTAs. Two tile-assignment modes:
//   balanced=0: grid-stride over flattened (op,batch,by,bx) tile list
//   balanced=1: closed-form balanced schedule for the g123 shape
//               (nL light 16-chunk tiles at ids [0,nL), nH heavy 32-chunk
//               tiles at ids [nL, nL+nH)). Max CTA load = 112 chunks.
// Block tile 128x128, 128 thr, 4 warps (2x2, warp 64x64), K-chunk 64
// (128B rows, XOR swizzle), cp.async 3-stage, ldmatrix.x4 + reg dbuf.
// biasMode: 0=none, 1=col, 2=row. outMode: 0=f16, 1=f32, 2=f16*SCALE.
// ---------------------------------------------------------------------------
#define STAGE_BYTES 32768                 // A 16KB + B 16KB
#define NSTAGE 3
#define SMEM_DYN   (NSTAGE * STAGE_BYTES) // 96 KB

#define ATT_SCALE 0.022097086912079612f   // 1/sqrt(2048)

struct GOp {
    const __half* A; const __half* B; const float* bias; void* C;
    long long sA, sB, sC;
    int K, lda, ldb, ldc, biasMode, outMode, nbx, ntb /*nbx*nby*/, off;
};
struct GParams { GOp op[3]; int nops; int total; int balanced; int nH; int nL; };

__device__ __forceinline__ void cp_tile_h(uint32_t base, const __half* g, int ld, int tid)
{
    #pragma unroll
    for (int l = 0; l < 8; l++) {
        int idx = tid + l * 128;          // 0..1023
        int r  = idx >> 3;                // 0..127
        int cb = (idx & 7) << 4;          // byte col 0..112
        uint32_t dst = base + r * 128 + (cb ^ ((r & 7) << 4));
        const __half* src = g + (long long)r * ld + (cb >> 1);
        asm volatile("cp.async.cg.shared.global [%0], [%1], 16;"
                     :: "r"(dst), "l"(src) : "memory");
    }
}

__global__ void __launch_bounds__(128, 2)
gemm_any(GParams P)
{
    extern __shared__ char sm[];
    const uint32_t smem0 = smem_u32(sm);

    const int tid  = threadIdx.x;
    const int lane = tid & 31;
    const int wid  = tid >> 5;
    const int wm   = (wid & 1) * 64;
    const int wn   = (wid >> 1) * 64;
    const int g    = lane >> 2;
    const int tc   = lane & 3;

    // ldmatrix per-lane address components
    const int arow = (lane & 15);
    const int akx  = (lane >> 4) << 4;
    const int brow = (lane & 7) + ((lane >> 4) & 1) * 8;
    const int bkx  = ((lane >> 3) & 1) << 4;

    // balanced schedule parameters (computed once)
    int h2 = 0, myH = 0, hFirst = 0, lBase = 0, myL = 0;
    if (P.balanced) {
        const int c = blockIdx.x;
        h2 = P.nH - (int)gridDim.x;
        if (c < h2) { myH = 2; hFirst = c; lBase = 3 * c; myL = 3; }
        else {
            myH = 1; hFirst = h2 + c;
            lBase = 3 * h2 + 5 * (c - h2);
            myL = P.nL - lBase;
            myL = myL < 0 ? 0 : (myL > 5 ? 5 : myL);
        }
    }

    for (int iter = 0;; iter++) {
        int t;
        if (P.balanced) {
            if (iter >= myH + myL) break;
            if (iter < myH) t = P.nL + ((iter == 0) ? hFirst : hFirst + h2);
            else            t = lBase + (iter - myH);
        } else {
            t = blockIdx.x + iter * gridDim.x;
            if (t >= P.total) break;
        }

        int oi = 0;
        if (P.nops > 1 && t >= P.op[1].off) oi = 1;
        if (P.nops > 2 && t >= P.op[2].off) oi = 2;
        const GOp o = P.op[oi];
        int rem = t - o.off;
        const int batch = rem / o.ntb;
        rem -= batch * o.ntb;
        const int bx = rem % o.nbx;
        const int by = rem / o.nbx;

        const __half* A = o.A + (long long)batch * o.sA + (long long)(by * 128) * o.lda;
        const __half* B = o.B + (long long)batch * o.sB + (long long)(bx * 128) * o.ldb;

        float acc[4][8][4];
        #pragma unroll
        for (int i = 0; i < 4; i++)
            #pragma unroll
            for (int j = 0; j < 8; j++)
                #pragma unroll
                for (int k = 0; k < 4; k++) acc[i][j][k] = 0.f;

        const int nk = o.K >> 6;          // K-chunks of 64

        __syncthreads();                  // smem stages free from previous tile
        cp_tile_h(smem0,         A, o.lda, tid);
        cp_tile_h(smem0 + 16384, B, o.ldb, tid);
        CP_COMMIT();
        cp_tile_h(smem0 + STAGE_BYTES,         A + 64, o.lda, tid);
        cp_tile_h(smem0 + STAGE_BYTES + 16384, B + 64, o.ldb, tid);
        CP_COMMIT();

        int s = 0;
        for (int i = 0; i < nk; i++) {
            if (i + 1 < nk) CP_WAIT(1); else CP_WAIT(0);
            __syncthreads();
            if (i + 2 < nk) {
                int s2 = s + 2; if (s2 >= NSTAGE) s2 -= NSTAGE;
                const uint32_t nb = smem0 + s2 * STAGE_BYTES;
                cp_tile_h(nb,         A + (i + 2) * 64, o.lda, tid);
                cp_tile_h(nb + 16384, B + (i + 2) * 64, o.ldb, tid);
                CP_COMMIT();
            }

            const uint32_t As = smem0 + s * STAGE_BYTES;
            const uint32_t Bs = As + 16384;

            unsigned a0[4][4], b0[4][4], a1[4][4], b1[4][4];
            #pragma unroll
            for (int mf = 0; mf < 4; mf++) {
                int r = wm + mf * 16 + arow;
                ldm_x4(a0[mf], As + r * 128 + ((0 + akx) ^ ((r & 7) << 4)));
            }
            #pragma unroll
            for (int p = 0; p < 4; p++) {
                int r = wn + p * 16 + brow;
                ldm_x4(b0[p], Bs + r * 128 + ((0 + bkx) ^ ((r & 7) << 4)));
            }
            #pragma unroll
            for (int ks = 0; ks < 4; ks++) {
                unsigned (&ac)[4][4] = (ks & 1) ? a1 : a0;
                unsigned (&bc)[4][4] = (ks & 1) ? b1 : b0;
                unsigned (&an)[4][4] = (ks & 1) ? a0 : a1;
                unsigned (&bn)[4][4] = (ks & 1) ? b0 : b1;
                if (ks < 3) {
                    const int kb = (ks + 1) * 32;
                    #pragma unroll
                    for (int mf = 0; mf < 4; mf++) {
                        int r = wm + mf * 16 + arow;
                        ldm_x4(an[mf], As + r * 128 + ((kb + akx) ^ ((r & 7) << 4)));
                    }
                    #pragma unroll
                    for (int p = 0; p < 4; p++) {
                        int r = wn + p * 16 + brow;
                        ldm_x4(bn[p], Bs + r * 128 + ((kb + bkx) ^ ((r & 7) << 4)));
                    }
                }
                #pragma unroll
                for (int mf = 0; mf < 4; mf++)
                    #pragma unroll
                    for (int p = 0; p < 4; p++) {
                        mma_f16(acc[mf][2 * p],     ac[mf], &bc[p][0]);
                        mma_f16(acc[mf][2 * p + 1], ac[mf], &bc[p][2]);
                    }
            }
            if (++s == NSTAGE) s = 0;
        }

        // ------------------------- epilogue ---------------------------------
        #pragma unroll
        for (int mf = 0; mf < 4; mf++) {
            #pragma unroll
            for (int nf = 0; nf < 8; nf++) {
                const int r0 = by * 128 + wm + mf * 16 + g;
                const int c  = bx * 128 + wn + nf * 8 + 2 * tc;
                float v0 = acc[mf][nf][0], v1 = acc[mf][nf][1];
                float v2 = acc[mf][nf][2], v3 = acc[mf][nf][3];
                if (o.biasMode == 1) {
                    const float b0 = o.bias[c], b1 = o.bias[c + 1];
                    v0 += b0; v1 += b1; v2 += b0; v3 += b1;
                } else if (o.biasMode == 2) {
                    const float br0 = o.bias[r0], br1 = o.bias[r0 + 8];
                    v0 += br0; v1 += br0; v2 += br1; v3 += br1;
                }
                if (o.outMode == 1) {
                    float* Cb = (float*)o.C + (long long)batch * o.sC;
                    *reinterpret_cast<float2*>(Cb + (long long)r0 * o.ldc + c)       = make_float2(v0, v1);
                    *reinterpret_cast<float2*>(Cb + (long long)(r0 + 8) * o.ldc + c) = make_float2(v2, v3);
                } else {
                    const float scl = (o.outMode == 2) ? ATT_SCALE : 1.f;
                    __half* Cb = (__half*)o.C + (long long)batch * o.sC;
                    *reinterpret_cast<__half2*>(Cb + (long long)r0 * o.ldc + c)       = __floats2half2_rn(v0 * scl, v1 * scl);
                    *reinterpret_cast<__half2*>(Cb + (long long)(r0 + 8) * o.ldc + c) = __floats2half2_rn(v2 * scl, v3 * scl);
                }
            }
        }
    }
}

// ------------------------- masked softmax over k -----------------------------
// Vectorized: thread t owns 8 contiguous elems; warp-shuffle reductions.
__global__ void softmax_kernel(const __half* __restrict__ lg,
                               __half* __restrict__ attn_h,
                               const void* __restrict__ mask_raw)
{
    const long long row = blockIdx.x;
    const int t = threadIdx.x, lane = t & 31, wid = t >> 5;
    const int mode = g_mask_mode;

    // logits: 8 contiguous halves per thread
    uint4 raw = reinterpret_cast<const uint4*>(lg + row * CDIM)[t];
    float v[8];
    {
        __half2 h0 = *reinterpret_cast<__half2*>(&raw.x);
        __half2 h1 = *reinterpret_cast<__half2*>(&raw.y);
        __half2 h2 = *reinterpret_cast<__half2*>(&raw.z);
        __half2 h3 = *reinterpret_cast<__half2*>(&raw.w);
        v[0] = __low2float(h0); v[1] = __high2float(h0);
        v[2] = __low2float(h1); v[3] = __high2float(h1);
        v[4] = __low2float(h2); v[5] = __high2float(h2);
        v[6] = __low2float(h3); v[7] = __high2float(h3);
    }

    // mask: bit i of msk = element masked
    unsigned msk = 0;
    if (mode == 0) {
        uint2 m = reinterpret_cast<const uint2*>(
            (const unsigned char*)mask_raw + row * CDIM)[t];
        #pragma unroll
        for (int i = 0; i < 4; i++) {
            if ((m.x >> (8 * i)) & 0xFF) msk |= 1u << i;
            if ((m.y >> (8 * i)) & 0xFF) msk |= 1u << (4 + i);
        }
    } else {
        const uint4* mw = reinterpret_cast<const uint4*>(mask_raw) + row * (CDIM / 4);
        uint4 a = mw[2 * t], b = mw[2 * t + 1];
        if (a.x) msk |= 1u;        if (a.y) msk |= 2u;
        if (a.z) msk |= 4u;        if (a.w) msk |= 8u;
        if (b.x) msk |= 16u;       if (b.y) msk |= 32u;
        if (b.z) msk |= 64u;       if (b.w) msk |= 128u;
    }

    float lmax = -INFINITY;
    #pragma unroll
    for (int i = 0; i < 8; i++) {
        if (msk & (1u << i)) v[i] = -INFINITY;
        lmax = fmaxf(lmax, v[i]);
    }
    #pragma unroll
    for (int o = 16; o > 0; o >>= 1)
        lmax = fmaxf(lmax, __shfl_xor_sync(0xFFFFFFFFu, lmax, o));

    __shared__ float smax[8], ssum[8];
    if (lane == 0) smax[wid] = lmax;
    __syncthreads();
    float rmax = smax[0];
    #pragma unroll
    for (int i = 1; i < 8; i++) rmax = fmaxf(rmax, smax[i]);

    float lsum = 0.f;
    #pragma unroll
    for (int i = 0; i < 8; i++) {
        v[i] = (msk & (1u << i)) ? 0.f : __expf(v[i] - rmax);
        lsum += v[i];
    }
    #pragma unroll
    for (int o = 16; o > 0; o >>= 1)
        lsum += __shfl_xor_sync(0xFFFFFFFFu, lsum, o);
    if (lane == 0) ssum[wid] = lsum;
    __syncthreads();
    float tot = 0.f;
    #pragma unroll
    for (int i = 0; i < 8; i++) tot += ssum[i];
    const float inv = 1.f / tot;

    uint4 outw;
    {
        __half2 h0 = __floats2half2_rn(v[0] * inv, v[1] * inv);
        __half2 h1 = __floats2half2_rn(v[2] * inv, v[3] * inv);
        __half2 h2 = __floats2half2_rn(v[4] * inv, v[5] * inv);
        __half2 h3 = __floats2half2_rn(v[6] * inv, v[7] * inv);
        outw.x = *reinterpret_cast<unsigned*>(&h0);
        outw.y = *reinterpret_cast<unsigned*>(&h1);
        outw.z = *reinterpret_cast<unsigned*>(&h2);
        outw.w = *reinterpret_cast<unsigned*>(&h3);
    }
    reinterpret_cast<uint4*>(attn_h + row * CDIM)[t] = outw;
}

// ---------------------------------------------------------------------------
extern "C" void kernel_launch(void* const* d_in, const int* in_sizes, int n_in,
                              void* d_out, int out_size)
{
    const float* x     = (const float*)d_in[0];   // [B,C,E]
    const float* fc_w  = (const float*)d_in[1];   // [E,E]
    const float* fc_b  = (const float*)d_in[2];   // [E]
    const float* alt_w = (const float*)d_in[3];   // [C,C]
    const float* alt_b = (const float*)d_in[4];   // [C]
    const float* v_w   = (const float*)d_in[5];   // [E,E]
    const float* v_b   = (const float*)d_in[6];   // [E]
    const void*  mask  = d_in[7];                 // [B,C,C] bool (encoding detected)
    float* out = (float*)d_out;                   // [B,C,E]

    __half *xh, *xTh, *yh, *zh, *vxTh, *fwh, *vwh, *awh, *lgh, *attnh;
    cudaGetSymbolAddress((void**)&xh,    g_xh);
    cudaGetSymbolAddress((void**)&xTh,   g_xTh);
    cudaGetSymbolAddress((void**)&yh,    g_yh);
    cudaGetSymbolAddress((void**)&zh,    g_zh);
    cudaGetSymbolAddress((void**)&vxTh,  g_vxTh);
    cudaGetSymbolAddress((void**)&fwh,   g_fwh);
    cudaGetSymbolAddress((void**)&vwh,   g_vwh);
    cudaGetSymbolAddress((void**)&awh,   g_awh);
    cudaGetSymbolAddress((void**)&lgh,   g_lgh);
    cudaGetSymbolAddress((void**)&attnh, g_attnh);

    cudaFuncSetAttribute(gemm_any, cudaFuncAttributeMaxDynamicSharedMemorySize, SMEM_DYN);

    int smCount = 148;
    {
        int dev = 0;
        cudaGetDevice(&dev);
        cudaDeviceGetAttribute(&smCount, cudaDevAttrMultiProcessorCount, dev);
    }
    const int gridP = smCount * 2;       // persistent grid (2 CTAs/SM resident)

    const long long sCE = (long long)CDIM * EDIM;
    const long long sCC = (long long)CDIM * CDIM;

    // 0) combined prep: dual transpose of x + weight conversions + mask detect
    prep_kernel<<<NTRB + 1024, 256>>>(
        x, xh, xTh,
        (const float4*)fc_w,  (__half2*)fwh, (EDIM * EDIM) / 4,
        (const float4*)v_w,   (__half2*)vwh, (EDIM * EDIM) / 4,
        (const float4*)alt_w, (__half2*)awh, (CDIM * CDIM) / 4,
        (const unsigned int*)mask);

    // 1-3) merged independent GEMMs, balanced closed-form schedule (1536 tiles)
    {
        GParams P; P.nops = 3; P.total = 1536;
        P.nH = 512; P.nL = 1024;
        // balanced schedule valid when 3*(nH-gridP) <= nL and 0 < nH-gridP
        P.balanced = (gridP >= 176 && gridP < 512) ? 1 : 0;
        P.op[0] = { xh,  fwh, fc_b,  yh,   sCE, 0,   sCE, EDIM, EDIM, EDIM, EDIM, 1, 0, EDIM / 128, (EDIM / 128) * (CDIM / 128), 0 };
        P.op[1] = { vwh, xh,  v_b,   vxTh, 0,   sCE, sCE, EDIM, EDIM, EDIM, CDIM, 2, 0, CDIM / 128, (CDIM / 128) * (EDIM / 128), 512 };
        P.op[2] = { awh, xTh, alt_b, zh,   0,   sCE, sCE, CDIM, CDIM, CDIM, EDIM, 2, 0, EDIM / 128, (EDIM / 128) * (CDIM / 128), 1024 };
        gemm_any<<<gridP, 128, SMEM_DYN>>>(P);
    }

    // 4) logits[c,k] = (sum_e y[c,e]*z[k,e]) * 1/sqrt(C)  -> f16  (1024 tiles)
    {
        GParams P; P.nops = 1; P.total = 1024; P.balanced = 0; P.nH = 0; P.nL = 0;
        P.op[0] = { yh, zh, nullptr, lgh, sCE, sCE, sCC, EDIM, EDIM, EDIM, CDIM, 0, 2, CDIM / 128, (CDIM / 128) * (CDIM / 128), 0 };
        gemm_any<<<gridP, 128, SMEM_DYN>>>(P);
    }

    // 5) masked softmax over k -> fp16 weights
    softmax_kernel<<<BATCH * CDIM, 256>>>(lgh, attnh, mask);

    // 6) out[c,e] = sum_k attn[c,k]*vxT[e,k]  (f32 out, 512 tiles)
    {
        GParams P; P.nops = 1; P.total = 512; P.balanced = 0; P.nH = 0; P.nL = 0;
        P.op[0] = { attnh, vxTh, nullptr, out, sCC, sCE, sCE, CDIM, CDIM, CDIM, EDIM, 0, 1, EDIM / 128, (EDIM / 128) * (CDIM / 128), 0 };
        gemm_any<<<gridP, 128, SMEM_DYN>>>(P);
    }
}